// round 15
// baseline (speedup 1.0000x reference)
#include <cuda_runtime.h>
#include <cuda_fp16.h>
#include <cstdint>

#define Nn     8192
#define FIN    512
#define FOUT   256
#define LALPHA 0.2f
#define M_TILE 128
#define KC     64
#define NBLK   (Nn / M_TILE)          // 64 row blocks
#define CPB    (Nn / KC)              // 128 chunks per row block
#define TOTSLOT (NBLK * CPB)          // 8192
#define NCTA   148

// attn smem layout (words)
#define WT_STRIDE_H 72                // half-tile k-stride (halfs) = 144 B rows
#define WHTILE_WORDS (FOUT * (WT_STRIDE_H / 2))   // 256*36 = 9216
#define ADJ_STRIDE 68
#define ADJTILE_WORDS (M_TILE * ADJ_STRIDE)       // 8704
#define SM_ADJ (2 * WHTILE_WORDS)                 // 18432
#define SM_FBD (SM_ADJ + 2 * ADJTILE_WORDS)       // 35840
#define SM_PS  (SM_FBD + 2 * 192)                 // 36224
#define PS_WORDS (M_TILE * (WT_STRIDE_H / 2))     // 128*36 = 4608
#define SMEM_DYN ((SM_PS + PS_WORDS) * 4)         // 163328 B

// gemm_wh_mma tiles
#define GW_STRIDE 264
#define GWTILE_WORDS (KC * GW_STRIDE)             // 16896
#define GM      64
#define HS      68
#define HS_WORDS (GM * HS)                        // 4352
#define GSM_A   (2 * HS_WORDS + 2 * GWTILE_WORDS)
#define GSMEM_DYN ((GSM_A + 512) * 4)             // 172032 B

// ---------------- scratch (device globals: allowed) ----------------
__device__ __half d_WhhT[(size_t)FOUT * Nn];         // 4 MB half, [n][j]
__device__ float d_Wr[(size_t)FIN * FOUT];           // tf32-rounded W
__device__ float d_f1[Nn];
__device__ float d_f2[Nn];
__device__ float d_A[Nn];
__device__ float d_C[Nn];
__device__ float d_B[Nn];
__device__ float d_D[Nn];
__device__ int   d_gmaxkey;
__device__ float d_num[(size_t)Nn * FOUT];           // 8 MB (atomic accum)
__device__ float d_ssum[Nn];

__device__ __forceinline__ uint32_t tf32_bits(float x) {
    uint32_t r; asm("cvt.rna.tf32.f32 %0, %1;" : "=r"(r) : "f"(x)); return r;
}
__device__ __forceinline__ void mma_tf32(float* d, uint32_t a0, uint32_t a1,
                                         uint32_t a2, uint32_t a3,
                                         uint32_t b0, uint32_t b1) {
    asm volatile(
        "mma.sync.aligned.m16n8k8.row.col.f32.tf32.tf32.f32 "
        "{%0,%1,%2,%3}, {%4,%5,%6,%7}, {%8,%9}, {%0,%1,%2,%3};"
        : "+f"(d[0]), "+f"(d[1]), "+f"(d[2]), "+f"(d[3])
        : "r"(a0), "r"(a1), "r"(a2), "r"(a3), "r"(b0), "r"(b1));
}
__device__ __forceinline__ void mma_f16(float* d, uint32_t a0, uint32_t a1,
                                        uint32_t a2, uint32_t a3,
                                        uint32_t b0, uint32_t b1) {
    asm volatile(
        "mma.sync.aligned.m16n8k16.row.col.f32.f16.f16.f32 "
        "{%0,%1,%2,%3}, {%4,%5,%6,%7}, {%8,%9}, {%0,%1,%2,%3};"
        : "+f"(d[0]), "+f"(d[1]), "+f"(d[2]), "+f"(d[3])
        : "r"(a0), "r"(a1), "r"(a2), "r"(a3), "r"(b0), "r"(b1));
}
__device__ __forceinline__ uint32_t smem_u32(const void* p) {
    uint32_t a;
    asm("{ .reg .u64 t; cvta.to.shared.u64 t, %1; cvt.u32.u64 %0, t; }"
        : "=r"(a) : "l"(p));
    return a;
}
__device__ __forceinline__ void cp_async16(uint32_t sa, const void* g) {
    asm volatile("cp.async.ca.shared.global [%0], [%1], 16;" :: "r"(sa), "l"(g) : "memory");
}
__device__ __forceinline__ void cp_commit() {
    asm volatile("cp.async.commit_group;" ::: "memory");
}
template <int N> __device__ __forceinline__ void cp_wait() {
    asm volatile("cp.async.wait_group %0;" :: "n"(N) : "memory");
}

// ---------------- init: zero accumulators + round W ----------------
__global__ void init_kernel(const float* __restrict__ W) {
    if (blockIdx.x == 0 && threadIdx.x == 0) d_gmaxkey = (int)0x80000000;
    size_t i = ((size_t)blockIdx.x * 256 + threadIdx.x) * 4;
    *(float4*)&d_num[i] = make_float4(0.f, 0.f, 0.f, 0.f);
    if (i < Nn)
        *(float4*)&d_ssum[i] = make_float4(0.f, 0.f, 0.f, 0.f);
    if (i < (size_t)FIN * FOUT) {
        float4 v = *(const float4*)&W[i];
        float4 o;
        o.x = __uint_as_float(tf32_bits(v.x));
        o.y = __uint_as_float(tf32_bits(v.y));
        o.z = __uint_as_float(tf32_bits(v.z));
        o.w = __uint_as_float(tf32_bits(v.w));
        *(float4*)&d_Wr[i] = o;
    }
}

// ---------------- Wh = h @ W via mma.sync tf32 (+ fused f1/f2/max) ----------------
__device__ __forceinline__ void stage_g(uint32_t sbase, const float* __restrict__ h,
                                        int i0, int c, int t) {
    int buf = c & 1;
    int k0  = c * KC;
    uint32_t hb = sbase + (uint32_t)(buf * HS_WORDS * 4);
#pragma unroll
    for (int u = 0; u < 4; u++) {
        int f = u * 256 + t;
        int row = f >> 4, seg = (f & 15) << 2;
        cp_async16(hb + (uint32_t)((row * HS + seg) * 4),
                   &h[(size_t)(i0 + row) * FIN + k0 + seg]);
    }
    uint32_t wb = sbase + (uint32_t)((2 * HS_WORDS + buf * GWTILE_WORDS) * 4);
#pragma unroll
    for (int u = 0; u < 16; u++) {
        int f = u * 256 + t;
        int row = f >> 6, c4 = (f & 63) << 2;
        cp_async16(wb + (uint32_t)((row * GW_STRIDE + c4) * 4),
                   &d_Wr[(size_t)(k0 + row) * FOUT + c4]);
    }
}

__global__ void __launch_bounds__(256, 1) gemm_wh_mma(const float* __restrict__ h,
                                                      const float* __restrict__ a) {
    extern __shared__ float gsm[];
    uint32_t sbase = smem_u32(gsm);
    float* as = gsm + GSM_A;   // a1[256] then a2[256]

    int t    = threadIdx.x;
    int lane = t & 31, wid = t >> 5;
    int mstrip = wid >> 1, nhalf = wid & 1;
    int gID = lane >> 2, tID = lane & 3;
    int r0t = mstrip * 16 + gID;
    int i0  = blockIdx.x * GM;

    if (t < 128) *(float4*)&as[t * 4] = *(const float4*)&a[t * 4];

    float acc[16][4];
#pragma unroll
    for (int n = 0; n < 16; n++)
#pragma unroll
        for (int u = 0; u < 4; u++) acc[n][u] = 0.f;

    stage_g(sbase, h, i0, 0, t);
    cp_commit();

    for (int c = 0; c < FIN / KC; c++) {
        int buf = c & 1;
        cp_wait<0>();
        __syncthreads();
        if (c + 1 < FIN / KC) {
            stage_g(sbase, h, i0, c + 1, t);
            cp_commit();
        }
        const float* hs = gsm + buf * HS_WORDS;
        const float* Wb = gsm + 2 * HS_WORDS + buf * GWTILE_WORDS;
#pragma unroll
        for (int k = 0; k < 8; k++) {
            int kc = tID + 8 * k;
            uint32_t a0 = tf32_bits(hs[(r0t)     * HS + kc]);
            uint32_t a1 = tf32_bits(hs[(r0t + 8) * HS + kc]);
            uint32_t a2 = tf32_bits(hs[(r0t)     * HS + kc + 4]);
            uint32_t a3 = tf32_bits(hs[(r0t + 8) * HS + kc + 4]);
            int krow = k * 8 + tID;
#pragma unroll
            for (int n = 0; n < 16; n++) {
                int n0 = nhalf * 128 + n * 8 + gID;
                uint32_t b0 = __float_as_uint(Wb[krow * GW_STRIDE + n0]);
                uint32_t b1 = __float_as_uint(Wb[(krow + 4) * GW_STRIDE + n0]);
                mma_tf32(acc[n], a0, a1, a2, a3, b0, b1);
            }
        }
        __syncthreads();
    }

    // epilogue: half WhhT (transposed [n][j]) + fused f1/f2 + block max(f2)
    float s1a = 0.f, s2a = 0.f, s1b = 0.f, s2b = 0.f;
    int cb = nhalf * 128 + tID * 2;
    int ia  = i0 + r0t, ib2 = i0 + r0t + 8;
#pragma unroll
    for (int n = 0; n < 16; n++) {
        int cc = cb + n * 8;
        d_WhhT[(size_t)cc * Nn + ia]        = __float2half(acc[n][0]);
        d_WhhT[(size_t)(cc + 1) * Nn + ia]  = __float2half(acc[n][1]);
        d_WhhT[(size_t)cc * Nn + ib2]       = __float2half(acc[n][2]);
        d_WhhT[(size_t)(cc + 1) * Nn + ib2] = __float2half(acc[n][3]);
        float a10 = as[cc], a11 = as[cc + 1];
        float a20 = as[256 + cc], a21 = as[256 + cc + 1];
        s1a += acc[n][0] * a10 + acc[n][1] * a11;
        s2a += acc[n][0] * a20 + acc[n][1] * a21;
        s1b += acc[n][2] * a10 + acc[n][3] * a11;
        s2b += acc[n][2] * a20 + acc[n][3] * a21;
    }
#pragma unroll
    for (int o = 1; o <= 2; o <<= 1) {
        s1a += __shfl_xor_sync(0xffffffffu, s1a, o);
        s2a += __shfl_xor_sync(0xffffffffu, s2a, o);
        s1b += __shfl_xor_sync(0xffffffffu, s1b, o);
        s2b += __shfl_xor_sync(0xffffffffu, s2b, o);
    }
    if (nhalf == 1 && tID == 0) {
        gsm[r0t]       = s1a;  gsm[64 + r0t]      = s2a;
        gsm[r0t + 8]   = s1b;  gsm[64 + r0t + 8]  = s2b;
    }
    __syncthreads();
    float mx = -3.0e38f;
    if (nhalf == 0 && tID == 0) {
        float f1t = s1a + gsm[r0t],     f2t = s2a + gsm[64 + r0t];
        float f1u = s1b + gsm[r0t + 8], f2u = s2b + gsm[64 + r0t + 8];
        d_f1[i0 + r0t]     = f1t;  d_f2[i0 + r0t]     = f2t;
        d_f1[i0 + r0t + 8] = f1u;  d_f2[i0 + r0t + 8] = f2u;
        mx = fmaxf(f2t, f2u);
    }
#pragma unroll
    for (int o = 16; o; o >>= 1)
        mx = fmaxf(mx, __shfl_xor_sync(0xffffffffu, mx, o));
    if (lane == 0) gsm[128 + wid] = mx;
    __syncthreads();
    if (t == 0) {
        float m = gsm[128];
#pragma unroll
        for (int w = 1; w < 8; w++) m = fmaxf(m, gsm[128 + w]);
        int b = __float_as_int(m);
        int key = b >= 0 ? b : (b ^ 0x7fffffff);
        atomicMax(&d_gmaxkey, key);
    }
}

// ---------------- factorized softmax weights ----------------
__global__ void pexp_kernel() {
    int i = blockIdx.x * 256 + threadIdx.x;
    int kk = d_gmaxkey;
    float gm = __int_as_float(kk >= 0 ? kk : (kk ^ 0x7fffffff));
    float f1 = d_f1[i], f2 = d_f2[i];
    float u  = f1 + gm;
    float m  = u > 0.f ? u : LALPHA * u;
    d_A[i] = __expf(u - m);
    d_C[i] = __expf(LALPHA * u - m);
    float v = f2 - gm;
    d_B[i] = __expf(v);
    d_D[i] = __expf(LALPHA * v);
}

// ---------------- staging helpers (cp.async) ----------------
__device__ __forceinline__ void stage_slot(uint32_t sbase, const int* adj,
                                           int s, int t) {
    int buf = s & 1;
    int ib  = s >> 7;
    int jg  = (s & (CPB - 1)) * KC;
    // WhT half tile [256 n][64 j], stride 72 halfs (144 B)
    uint32_t wb = sbase + (uint32_t)(buf * WHTILE_WORDS * 4);
#pragma unroll
    for (int u = 0; u < 4; u++) {
        int f = u * 512 + t;                  // 0..2047
        int row = f >> 3, seg = f & 7;        // 8 x 16B per row
        cp_async16(wb + (uint32_t)(row * 144 + seg * 16),
                   &d_WhhT[(size_t)row * Nn + jg + seg * 8]);
    }
    uint32_t ab = sbase + (uint32_t)((SM_ADJ + buf * ADJTILE_WORDS) * 4);
    const int* abase = adj + (size_t)ib * M_TILE * Nn + jg;
#pragma unroll
    for (int u = 0; u < 4; u++) {
        int f = u * 512 + t;
        int row = f >> 4, seg = (f & 15) << 2;
        cp_async16(ab + (uint32_t)((row * ADJ_STRIDE + seg) * 4),
                   abase + (size_t)row * Nn + seg);
    }
    if (t < 48) {
        uint32_t fb = sbase + (uint32_t)((SM_FBD + buf * 192 + t * 4) * 4);
        const float* src = (t < 16) ? &d_f2[jg + t * 4]
                         : (t < 32) ? &d_B[jg + (t - 16) * 4]
                                    : &d_D[jg + (t - 32) * 4];
        cp_async16(fb, src);
    }
}

// ---------------- fused attention: P-in-smem + dual ldmatrix fp16 MMA ----------------
// 148 CTAs x 512 threads = 16 warps: 4 m-strips (32 rows) x 4 n-quarters (64 cols).
// Phase 1: each thread computes 16 P values once -> half2 -> Psm [128][72 halfs].
// Phase 2: A-frags (P) and B-frags (WhT) both via ldmatrix.x4; 64 HMMA/warp/chunk.
__global__ void __launch_bounds__(512, 1) attn_mma(const int* __restrict__ adj) {
    extern __shared__ float sm[];
    uint32_t sbase = smem_u32(sm);
    char* psmC = (char*)sm + SM_PS * 4;

    int t    = threadIdx.x;
    int lane = t & 31, wid = t >> 5;
    int mstrip = wid >> 2, nq = wid & 3;
    int gID = lane >> 2, tID = lane & 3;
    int mr  = mstrip * 32;

    // P-phase assignment: one row per 4 threads, 16 cols each
    int prow = t >> 2;
    int pc0  = (t & 3) << 4;

    // ldmatrix lane offsets
    int lq = lane >> 3, lr = lane & 7;
    int nB = ((lq >> 1) << 3) + lr, kB = (lq & 1) << 3;            // B quadrants
    uint32_t lmB_off = (uint32_t)(((nq * 64 + nB) * WT_STRIDE_H + kB) * 2);
    int rA = ((lq & 1) << 3) + lr, kA = (lq >> 1) << 3;            // A quadrants
    uint32_t lmA_off = (uint32_t)((rA * WT_STRIDE_H + kA) * 2);
    uint32_t psm_base = sbase + (uint32_t)(SM_PS * 4);

    int s0 = (int)(((long long)blockIdx.x * TOTSLOT) / NCTA);
    int s1 = (int)(((long long)(blockIdx.x + 1) * TOTSLOT) / NCTA);

    float acc[8][2][4];
#pragma unroll
    for (int n = 0; n < 8; n++)
#pragma unroll
        for (int mt = 0; mt < 2; mt++)
#pragma unroll
            for (int u = 0; u < 4; u++) acc[n][mt][u] = 0.f;
    float ssum = 0.f;

    float f1r = 0.f, Ar = 0.f, Cr = 0.f;
    int cur_ib = -1;

    stage_slot(sbase, adj, s0, t);
    cp_commit();

    for (int s = s0; s < s1; s++) {
        int ib = s >> 7;
        int buf = s & 1;

        if (ib != cur_ib) {
            if (cur_ib >= 0) {
                // flush ssum (lanes t, t^1, t^2 share prow)
                float sv = ssum + __shfl_xor_sync(0xffffffffu, ssum, 1);
                sv += __shfl_xor_sync(0xffffffffu, sv, 2);
                int base = cur_ib * M_TILE;
                if ((t & 3) == 0) atomicAdd(&d_ssum[base + prow], sv);
                ssum = 0.f;
                // flush acc
                float* np = &d_num[(size_t)base * FOUT];
#pragma unroll
                for (int n = 0; n < 8; n++) {
                    int cc = nq * 64 + n * 8 + tID * 2;
#pragma unroll
                    for (int mt = 0; mt < 2; mt++) {
                        int ra = mr + mt * 16 + gID;
                        atomicAdd(&np[(size_t)ra * FOUT + cc],           acc[n][mt][0]);
                        atomicAdd(&np[(size_t)ra * FOUT + cc + 1],       acc[n][mt][1]);
                        atomicAdd(&np[(size_t)(ra + 8) * FOUT + cc],     acc[n][mt][2]);
                        atomicAdd(&np[(size_t)(ra + 8) * FOUT + cc + 1], acc[n][mt][3]);
                        acc[n][mt][0] = 0.f; acc[n][mt][1] = 0.f;
                        acc[n][mt][2] = 0.f; acc[n][mt][3] = 0.f;
                    }
                }
            }
            int base = ib * M_TILE;
            f1r = d_f1[base + prow];
            Ar  = d_A[base + prow];
            Cr  = d_C[base + prow];
            cur_ib = ib;
        }

        cp_wait<0>();
        __syncthreads();   // staged bufs ready; MMA(s-1) retired -> Psm reusable

        if (s + 1 < s1) {
            stage_slot(sbase, adj, s + 1, t);
            cp_commit();
        }

        const int*   adjS = (const int*)(sm + SM_ADJ + buf * ADJTILE_WORDS);
        const float* fbd  = sm + SM_FBD + buf * 192;

        // ---- Phase 1: P tile (computed once) ----
        uint32_t pk[8];
#pragma unroll
        for (int u = 0; u < 4; u++) {
            int cc = pc0 + u * 4;
            int4   ad  = *(const int4*)&adjS[prow * ADJ_STRIDE + cc];
            float4 f2v = *(const float4*)&fbd[cc];
            float4 Bv  = *(const float4*)&fbd[64 + cc];
            float4 Dv  = *(const float4*)&fbd[128 + cc];
            float e0 = f1r + f2v.x, e1 = f1r + f2v.y;
            float e2 = f1r + f2v.z, e3 = f1r + f2v.w;
            float p0 = (ad.x > 0) ? (e0 > 0.f ? Ar * Bv.x : Cr * Dv.x) : 0.f;
            float p1 = (ad.y > 0) ? (e1 > 0.f ? Ar * Bv.y : Cr * Dv.y) : 0.f;
            float p2 = (ad.z > 0) ? (e2 > 0.f ? Ar * Bv.z : Cr * Dv.z) : 0.f;
            float p3 = (ad.w > 0) ? (e3 > 0.f ? Ar * Bv.w : Cr * Dv.w) : 0.f;
            ssum += (p0 + p1) + (p2 + p3);
            __half2 hh;
            hh = __floats2half2_rn(p0, p1); pk[2 * u]     = *(uint32_t*)&hh;
            hh = __floats2half2_rn(p2, p3); pk[2 * u + 1] = *(uint32_t*)&hh;
        }
        {
            char* dst = psmC + prow * 144 + pc0 * 2;
            *(uint4*)dst        = make_uint4(pk[0], pk[1], pk[2], pk[3]);
            *(uint4*)(dst + 16) = make_uint4(pk[4], pk[5], pk[6], pk[7]);
        }
        __syncthreads();   // P published

        // ---- Phase 2: MMA via dual ldmatrix ----
        uint32_t lmB = sbase + (uint32_t)(buf * WHTILE_WORDS * 4) + lmB_off;
        uint32_t lmA = psm_base + (uint32_t)(mr * 144) + lmA_off;
#pragma unroll
        for (int k = 0; k < 4; k++) {
            uint32_t av[2][4];
#pragma unroll
            for (int mt = 0; mt < 2; mt++) {
                asm volatile(
                    "ldmatrix.sync.aligned.m8n8.x4.shared.b16 {%0,%1,%2,%3}, [%4];"
                    : "=r"(av[mt][0]), "=r"(av[mt][1]), "=r"(av[mt][2]), "=r"(av[mt][3])
                    : "r"(lmA + (uint32_t)(mt * 16 * 144 + k * 32)));
            }
#pragma unroll
            for (int p = 0; p < 4; p++) {
                uint32_t b00, b01, b10, b11;
                asm volatile(
                    "ldmatrix.sync.aligned.m8n8.x4.shared.b16 {%0,%1,%2,%3}, [%4];"
                    : "=r"(b00), "=r"(b01), "=r"(b10), "=r"(b11)
                    : "r"(lmB + (uint32_t)(p * 16 * 144 + k * 32)));
                mma_f16(acc[2 * p][0],     av[0][0], av[0][1], av[0][2], av[0][3], b00, b01);
                mma_f16(acc[2 * p][1],     av[1][0], av[1][1], av[1][2], av[1][3], b00, b01);
                mma_f16(acc[2 * p + 1][0], av[0][0], av[0][1], av[0][2], av[0][3], b10, b11);
                mma_f16(acc[2 * p + 1][1], av[1][0], av[1][1], av[1][2], av[1][3], b10, b11);
            }
        }
    }

    // final flush
    {
        float sv = ssum + __shfl_xor_sync(0xffffffffu, ssum, 1);
        sv += __shfl_xor_sync(0xffffffffu, sv, 2);
        int base = cur_ib * M_TILE;
        if ((t & 3) == 0) atomicAdd(&d_ssum[base + prow], sv);
        float* np = &d_num[(size_t)base * FOUT];
#pragma unroll
        for (int n = 0; n < 8; n++) {
            int cc = nq * 64 + n * 8 + tID * 2;
#pragma unroll
            for (int mt = 0; mt < 2; mt++) {
                int ra = mr + mt * 16 + gID;
                atomicAdd(&np[(size_t)ra * FOUT + cc],           acc[n][mt][0]);
                atomicAdd(&np[(size_t)ra * FOUT + cc + 1],       acc[n][mt][1]);
                atomicAdd(&np[(size_t)(ra + 8) * FOUT + cc],     acc[n][mt][2]);
                atomicAdd(&np[(size_t)(ra + 8) * FOUT + cc + 1], acc[n][mt][3]);
            }
        }
    }
}

// ---------------- normalize + ELU (vectorized) ----------------
__global__ void elu_kernel(float* __restrict__ out) {
    int idx = blockIdx.x * 256 + threadIdx.x;     // one float4 per thread
    int row = idx >> 6;                           // 64 float4 per row
    float s = d_ssum[row];
    float4 v = *(const float4*)&d_num[(size_t)idx * 4];
    float4 o;
    float x;
    x = v.x / s; o.x = x > 0.f ? x : expm1f(x);
    x = v.y / s; o.y = x > 0.f ? x : expm1f(x);
    x = v.z / s; o.z = x > 0.f ? x : expm1f(x);
    x = v.w / s; o.w = x > 0.f ? x : expm1f(x);
    *(float4*)&out[(size_t)idx * 4] = o;
}

extern "C" void kernel_launch(void* const* d_in, const int* in_sizes, int n_in,
                              void* d_out, int out_size) {
    const float* h   = (const float*)d_in[0];
    const int*   adj = (const int*)d_in[1];
    const float* W   = (const float*)d_in[2];
    const float* a   = (const float*)d_in[3];
    float* out = (float*)d_out;

    cudaFuncSetAttribute(attn_mma, cudaFuncAttributeMaxDynamicSharedMemorySize, SMEM_DYN);
    cudaFuncSetAttribute(gemm_wh_mma, cudaFuncAttributeMaxDynamicSharedMemorySize, GSMEM_DYN);

    init_kernel<<<(Nn * FOUT) / 1024, 256>>>(W);
    gemm_wh_mma<<<Nn / GM, 256, GSMEM_DYN>>>(h, a);
    pexp_kernel<<<Nn / 256, 256>>>();
    attn_mma<<<NCTA, 512, SMEM_DYN>>>(adj);
    elu_kernel<<<(Nn * FOUT) / 1024, 256>>>(out);
}

// round 16
// speedup vs baseline: 1.0014x; 1.0014x over previous
#include <cuda_runtime.h>
#include <cuda_fp16.h>
#include <cstdint>

#define Nn     8192
#define FIN    512
#define FOUT   256
#define LALPHA 0.2f
#define M_TILE 128
#define KC     64
#define NBLK   (Nn / M_TILE)          // 64 row blocks
#define CPB    (Nn / KC)              // 128 chunks per row block
#define TOTSLOT (NBLK * CPB)          // 8192
#define NCTA   148

// attn smem layout (words)
#define WT_STRIDE_H 72                // half-tile k-stride (halfs) = 144 B rows
#define WHTILE_WORDS (FOUT * (WT_STRIDE_H / 2))   // 256*36 = 9216
#define ADJ_STRIDE 68
#define ADJTILE_WORDS (M_TILE * ADJ_STRIDE)       // 8704
#define SM_ADJ (2 * WHTILE_WORDS)                 // 18432
#define SM_FBD (SM_ADJ + 2 * ADJTILE_WORDS)       // 35840
#define SM_PS  (SM_FBD + 2 * 192)                 // 36224
#define PS_WORDS (M_TILE * (WT_STRIDE_H / 2))     // 128*36 = 4608
#define SMEM_DYN ((SM_PS + PS_WORDS) * 4)         // 163328 B

// gemm_wh_mma tiles
#define GW_STRIDE 264
#define GWTILE_WORDS (KC * GW_STRIDE)             // 16896
#define GM      64
#define HS      68
#define HS_WORDS (GM * HS)                        // 4352
#define GSM_A   (2 * HS_WORDS + 2 * GWTILE_WORDS)
#define GSMEM_DYN ((GSM_A + 512) * 4)             // 172032 B

// ---------------- scratch (device globals: allowed) ----------------
__device__ __half d_WhhT[(size_t)FOUT * Nn];         // 4 MB half, [n][j]
__device__ float d_Wr[(size_t)FIN * FOUT];           // tf32-rounded W
__device__ float d_f1[Nn];
__device__ float d_f2[Nn];
__device__ float d_A[Nn];
__device__ float d_C[Nn];
__device__ float d_B[Nn];
__device__ float d_D[Nn];
__device__ int   d_gmaxkey;
__device__ float d_num[(size_t)Nn * FOUT];           // 8 MB (atomic accum)
__device__ float d_ssum[Nn];

__device__ __forceinline__ uint32_t tf32_bits(float x) {
    uint32_t r; asm("cvt.rna.tf32.f32 %0, %1;" : "=r"(r) : "f"(x)); return r;
}
__device__ __forceinline__ void mma_tf32(float* d, uint32_t a0, uint32_t a1,
                                         uint32_t a2, uint32_t a3,
                                         uint32_t b0, uint32_t b1) {
    asm volatile(
        "mma.sync.aligned.m16n8k8.row.col.f32.tf32.tf32.f32 "
        "{%0,%1,%2,%3}, {%4,%5,%6,%7}, {%8,%9}, {%0,%1,%2,%3};"
        : "+f"(d[0]), "+f"(d[1]), "+f"(d[2]), "+f"(d[3])
        : "r"(a0), "r"(a1), "r"(a2), "r"(a3), "r"(b0), "r"(b1));
}
__device__ __forceinline__ void mma_f16(float* d, uint32_t a0, uint32_t a1,
                                        uint32_t a2, uint32_t a3,
                                        uint32_t b0, uint32_t b1) {
    asm volatile(
        "mma.sync.aligned.m16n8k16.row.col.f32.f16.f16.f32 "
        "{%0,%1,%2,%3}, {%4,%5,%6,%7}, {%8,%9}, {%0,%1,%2,%3};"
        : "+f"(d[0]), "+f"(d[1]), "+f"(d[2]), "+f"(d[3])
        : "r"(a0), "r"(a1), "r"(a2), "r"(a3), "r"(b0), "r"(b1));
}
__device__ __forceinline__ uint32_t smem_u32(const void* p) {
    uint32_t a;
    asm("{ .reg .u64 t; cvta.to.shared.u64 t, %1; cvt.u32.u64 %0, t; }"
        : "=r"(a) : "l"(p));
    return a;
}
__device__ __forceinline__ void cp_async16(uint32_t sa, const void* g) {
    asm volatile("cp.async.ca.shared.global [%0], [%1], 16;" :: "r"(sa), "l"(g) : "memory");
}
__device__ __forceinline__ void cp_commit() {
    asm volatile("cp.async.commit_group;" ::: "memory");
}
template <int N> __device__ __forceinline__ void cp_wait() {
    asm volatile("cp.async.wait_group %0;" :: "n"(N) : "memory");
}

// ---------------- init: zero accumulators + round W ----------------
__global__ void init_kernel(const float* __restrict__ W) {
    if (blockIdx.x == 0 && threadIdx.x == 0) d_gmaxkey = (int)0x80000000;
    size_t i = ((size_t)blockIdx.x * 256 + threadIdx.x) * 4;
    *(float4*)&d_num[i] = make_float4(0.f, 0.f, 0.f, 0.f);
    if (i < Nn)
        *(float4*)&d_ssum[i] = make_float4(0.f, 0.f, 0.f, 0.f);
    if (i < (size_t)FIN * FOUT) {
        float4 v = *(const float4*)&W[i];
        float4 o;
        o.x = __uint_as_float(tf32_bits(v.x));
        o.y = __uint_as_float(tf32_bits(v.y));
        o.z = __uint_as_float(tf32_bits(v.z));
        o.w = __uint_as_float(tf32_bits(v.w));
        *(float4*)&d_Wr[i] = o;
    }
}

// ---------------- Wh = h @ W via mma.sync tf32 (+ fused f1/f2/max) ----------------
__device__ __forceinline__ void stage_g(uint32_t sbase, const float* __restrict__ h,
                                        int i0, int c, int t) {
    int buf = c & 1;
    int k0  = c * KC;
    uint32_t hb = sbase + (uint32_t)(buf * HS_WORDS * 4);
#pragma unroll
    for (int u = 0; u < 4; u++) {
        int f = u * 256 + t;
        int row = f >> 4, seg = (f & 15) << 2;
        cp_async16(hb + (uint32_t)((row * HS + seg) * 4),
                   &h[(size_t)(i0 + row) * FIN + k0 + seg]);
    }
    uint32_t wb = sbase + (uint32_t)((2 * HS_WORDS + buf * GWTILE_WORDS) * 4);
#pragma unroll
    for (int u = 0; u < 16; u++) {
        int f = u * 256 + t;
        int row = f >> 6, c4 = (f & 63) << 2;
        cp_async16(wb + (uint32_t)((row * GW_STRIDE + c4) * 4),
                   &d_Wr[(size_t)(k0 + row) * FOUT + c4]);
    }
}

__global__ void __launch_bounds__(256, 1) gemm_wh_mma(const float* __restrict__ h,
                                                      const float* __restrict__ a) {
    extern __shared__ float gsm[];
    uint32_t sbase = smem_u32(gsm);
    float* as = gsm + GSM_A;   // a1[256] then a2[256]

    int t    = threadIdx.x;
    int lane = t & 31, wid = t >> 5;
    int mstrip = wid >> 1, nhalf = wid & 1;
    int gID = lane >> 2, tID = lane & 3;
    int r0t = mstrip * 16 + gID;
    int i0  = blockIdx.x * GM;

    if (t < 128) *(float4*)&as[t * 4] = *(const float4*)&a[t * 4];

    float acc[16][4];
#pragma unroll
    for (int n = 0; n < 16; n++)
#pragma unroll
        for (int u = 0; u < 4; u++) acc[n][u] = 0.f;

    stage_g(sbase, h, i0, 0, t);
    cp_commit();

    for (int c = 0; c < FIN / KC; c++) {
        int buf = c & 1;
        cp_wait<0>();
        __syncthreads();
        if (c + 1 < FIN / KC) {
            stage_g(sbase, h, i0, c + 1, t);
            cp_commit();
        }
        const float* hs = gsm + buf * HS_WORDS;
        const float* Wb = gsm + 2 * HS_WORDS + buf * GWTILE_WORDS;
#pragma unroll
        for (int k = 0; k < 8; k++) {
            int kc = tID + 8 * k;
            uint32_t a0 = tf32_bits(hs[(r0t)     * HS + kc]);
            uint32_t a1 = tf32_bits(hs[(r0t + 8) * HS + kc]);
            uint32_t a2 = tf32_bits(hs[(r0t)     * HS + kc + 4]);
            uint32_t a3 = tf32_bits(hs[(r0t + 8) * HS + kc + 4]);
            int krow = k * 8 + tID;
#pragma unroll
            for (int n = 0; n < 16; n++) {
                int n0 = nhalf * 128 + n * 8 + gID;
                uint32_t b0 = __float_as_uint(Wb[krow * GW_STRIDE + n0]);
                uint32_t b1 = __float_as_uint(Wb[(krow + 4) * GW_STRIDE + n0]);
                mma_tf32(acc[n], a0, a1, a2, a3, b0, b1);
            }
        }
        __syncthreads();
    }

    // epilogue: half WhhT (transposed [n][j]) + fused f1/f2 + block max(f2)
    float s1a = 0.f, s2a = 0.f, s1b = 0.f, s2b = 0.f;
    int cb = nhalf * 128 + tID * 2;
    int ia  = i0 + r0t, ib2 = i0 + r0t + 8;
#pragma unroll
    for (int n = 0; n < 16; n++) {
        int cc = cb + n * 8;
        d_WhhT[(size_t)cc * Nn + ia]        = __float2half(acc[n][0]);
        d_WhhT[(size_t)(cc + 1) * Nn + ia]  = __float2half(acc[n][1]);
        d_WhhT[(size_t)cc * Nn + ib2]       = __float2half(acc[n][2]);
        d_WhhT[(size_t)(cc + 1) * Nn + ib2] = __float2half(acc[n][3]);
        float a10 = as[cc], a11 = as[cc + 1];
        float a20 = as[256 + cc], a21 = as[256 + cc + 1];
        s1a += acc[n][0] * a10 + acc[n][1] * a11;
        s2a += acc[n][0] * a20 + acc[n][1] * a21;
        s1b += acc[n][2] * a10 + acc[n][3] * a11;
        s2b += acc[n][2] * a20 + acc[n][3] * a21;
    }
#pragma unroll
    for (int o = 1; o <= 2; o <<= 1) {
        s1a += __shfl_xor_sync(0xffffffffu, s1a, o);
        s2a += __shfl_xor_sync(0xffffffffu, s2a, o);
        s1b += __shfl_xor_sync(0xffffffffu, s1b, o);
        s2b += __shfl_xor_sync(0xffffffffu, s2b, o);
    }
    if (nhalf == 1 && tID == 0) {
        gsm[r0t]       = s1a;  gsm[64 + r0t]      = s2a;
        gsm[r0t + 8]   = s1b;  gsm[64 + r0t + 8]  = s2b;
    }
    __syncthreads();
    float mx = -3.0e38f;
    if (nhalf == 0 && tID == 0) {
        float f1t = s1a + gsm[r0t],     f2t = s2a + gsm[64 + r0t];
        float f1u = s1b + gsm[r0t + 8], f2u = s2b + gsm[64 + r0t + 8];
        d_f1[i0 + r0t]     = f1t;  d_f2[i0 + r0t]     = f2t;
        d_f1[i0 + r0t + 8] = f1u;  d_f2[i0 + r0t + 8] = f2u;
        mx = fmaxf(f2t, f2u);
    }
#pragma unroll
    for (int o = 16; o; o >>= 1)
        mx = fmaxf(mx, __shfl_xor_sync(0xffffffffu, mx, o));
    if (lane == 0) gsm[128 + wid] = mx;
    __syncthreads();
    if (t == 0) {
        float m = gsm[128];
#pragma unroll
        for (int w = 1; w < 8; w++) m = fmaxf(m, gsm[128 + w]);
        int b = __float_as_int(m);
        int key = b >= 0 ? b : (b ^ 0x7fffffff);
        atomicMax(&d_gmaxkey, key);
    }
}

// ---------------- factorized softmax weights ----------------
__global__ void pexp_kernel() {
    int i = blockIdx.x * 256 + threadIdx.x;
    int kk = d_gmaxkey;
    float gm = __int_as_float(kk >= 0 ? kk : (kk ^ 0x7fffffff));
    float f1 = d_f1[i], f2 = d_f2[i];
    float u  = f1 + gm;
    float m  = u > 0.f ? u : LALPHA * u;
    d_A[i] = __expf(u - m);
    d_C[i] = __expf(LALPHA * u - m);
    float v = f2 - gm;
    d_B[i] = __expf(v);
    d_D[i] = __expf(LALPHA * v);
}

// ---------------- staging helpers (cp.async) ----------------
__device__ __forceinline__ void stage_slot(uint32_t sbase, const int* adj,
                                           int s, int t) {
    int buf = s & 1;
    int ib  = s >> 7;
    int jg  = (s & (CPB - 1)) * KC;
    // WhT half tile [256 n][64 j], stride 72 halfs (144 B)
    uint32_t wb = sbase + (uint32_t)(buf * WHTILE_WORDS * 4);
#pragma unroll
    for (int u = 0; u < 4; u++) {
        int f = u * 512 + t;                  // 0..2047
        int row = f >> 3, seg = f & 7;        // 8 x 16B per row
        cp_async16(wb + (uint32_t)(row * 144 + seg * 16),
                   &d_WhhT[(size_t)row * Nn + jg + seg * 8]);
    }
    uint32_t ab = sbase + (uint32_t)((SM_ADJ + buf * ADJTILE_WORDS) * 4);
    const int* abase = adj + (size_t)ib * M_TILE * Nn + jg;
#pragma unroll
    for (int u = 0; u < 4; u++) {
        int f = u * 512 + t;
        int row = f >> 4, seg = (f & 15) << 2;
        cp_async16(ab + (uint32_t)((row * ADJ_STRIDE + seg) * 4),
                   abase + (size_t)row * Nn + seg);
    }
    if (t < 48) {
        uint32_t fb = sbase + (uint32_t)((SM_FBD + buf * 192 + t * 4) * 4);
        const float* src = (t < 16) ? &d_f2[jg + t * 4]
                         : (t < 32) ? &d_B[jg + (t - 16) * 4]
                                    : &d_D[jg + (t - 32) * 4];
        cp_async16(fb, src);
    }
}

// ---------------- fused attention: P-in-smem + dual ldmatrix fp16 MMA ----------------
// 148 CTAs x 512 threads = 16 warps: 4 m-strips (32 rows) x 4 n-quarters (64 cols).
// Phase 1: each thread computes 16 P values once -> half2 -> Psm [128][72 halfs].
// Phase 2: A-frags (P) and B-frags (WhT) both via ldmatrix.x4; 64 HMMA/warp/chunk.
__global__ void __launch_bounds__(512, 1) attn_mma(const int* __restrict__ adj) {
    extern __shared__ float sm[];
    uint32_t sbase = smem_u32(sm);
    char* psmC = (char*)sm + SM_PS * 4;

    int t    = threadIdx.x;
    int lane = t & 31, wid = t >> 5;
    int mstrip = wid >> 2, nq = wid & 3;
    int gID = lane >> 2, tID = lane & 3;
    int mr  = mstrip * 32;

    // P-phase assignment: one row per 4 threads, 16 cols each
    int prow = t >> 2;
    int pc0  = (t & 3) << 4;

    // ldmatrix lane offsets
    int lq = lane >> 3, lr = lane & 7;
    int nB = ((lq >> 1) << 3) + lr, kB = (lq & 1) << 3;            // B quadrants
    uint32_t lmB_off = (uint32_t)(((nq * 64 + nB) * WT_STRIDE_H + kB) * 2);
    int rA = ((lq & 1) << 3) + lr, kA = (lq >> 1) << 3;            // A quadrants
    uint32_t lmA_off = (uint32_t)((rA * WT_STRIDE_H + kA) * 2);
    uint32_t psm_base = sbase + (uint32_t)(SM_PS * 4);

    int s0 = (int)(((long long)blockIdx.x * TOTSLOT) / NCTA);
    int s1 = (int)(((long long)(blockIdx.x + 1) * TOTSLOT) / NCTA);

    float acc[8][2][4];
#pragma unroll
    for (int n = 0; n < 8; n++)
#pragma unroll
        for (int mt = 0; mt < 2; mt++)
#pragma unroll
            for (int u = 0; u < 4; u++) acc[n][mt][u] = 0.f;
    float ssum = 0.f;

    float f1r = 0.f, Ar = 0.f, Cr = 0.f;
    int cur_ib = -1;

    stage_slot(sbase, adj, s0, t);
    cp_commit();

    for (int s = s0; s < s1; s++) {
        int ib = s >> 7;
        int buf = s & 1;

        if (ib != cur_ib) {
            if (cur_ib >= 0) {
                // flush ssum (lanes t, t^1, t^2 share prow)
                float sv = ssum + __shfl_xor_sync(0xffffffffu, ssum, 1);
                sv += __shfl_xor_sync(0xffffffffu, sv, 2);
                int base = cur_ib * M_TILE;
                if ((t & 3) == 0) atomicAdd(&d_ssum[base + prow], sv);
                ssum = 0.f;
                // flush acc
                float* np = &d_num[(size_t)base * FOUT];
#pragma unroll
                for (int n = 0; n < 8; n++) {
                    int cc = nq * 64 + n * 8 + tID * 2;
#pragma unroll
                    for (int mt = 0; mt < 2; mt++) {
                        int ra = mr + mt * 16 + gID;
                        atomicAdd(&np[(size_t)ra * FOUT + cc],           acc[n][mt][0]);
                        atomicAdd(&np[(size_t)ra * FOUT + cc + 1],       acc[n][mt][1]);
                        atomicAdd(&np[(size_t)(ra + 8) * FOUT + cc],     acc[n][mt][2]);
                        atomicAdd(&np[(size_t)(ra + 8) * FOUT + cc + 1], acc[n][mt][3]);
                        acc[n][mt][0] = 0.f; acc[n][mt][1] = 0.f;
                        acc[n][mt][2] = 0.f; acc[n][mt][3] = 0.f;
                    }
                }
            }
            int base = ib * M_TILE;
            f1r = d_f1[base + prow];
            Ar  = d_A[base + prow];
            Cr  = d_C[base + prow];
            cur_ib = ib;
        }

        cp_wait<0>();
        __syncthreads();   // staged bufs ready; MMA(s-1) retired -> Psm reusable

        if (s + 1 < s1) {
            stage_slot(sbase, adj, s + 1, t);
            cp_commit();
        }

        const int*   adjS = (const int*)(sm + SM_ADJ + buf * ADJTILE_WORDS);
        const float* fbd  = sm + SM_FBD + buf * 192;

        // ---- Phase 1: P tile (computed once) ----
        uint32_t pk[8];
#pragma unroll
        for (int u = 0; u < 4; u++) {
            int cc = pc0 + u * 4;
            int4   ad  = *(const int4*)&adjS[prow * ADJ_STRIDE + cc];
            float4 f2v = *(const float4*)&fbd[cc];
            float4 Bv  = *(const float4*)&fbd[64 + cc];
            float4 Dv  = *(const float4*)&fbd[128 + cc];
            float e0 = f1r + f2v.x, e1 = f1r + f2v.y;
            float e2 = f1r + f2v.z, e3 = f1r + f2v.w;
            float p0 = (ad.x > 0) ? (e0 > 0.f ? Ar * Bv.x : Cr * Dv.x) : 0.f;
            float p1 = (ad.y > 0) ? (e1 > 0.f ? Ar * Bv.y : Cr * Dv.y) : 0.f;
            float p2 = (ad.z > 0) ? (e2 > 0.f ? Ar * Bv.z : Cr * Dv.z) : 0.f;
            float p3 = (ad.w > 0) ? (e3 > 0.f ? Ar * Bv.w : Cr * Dv.w) : 0.f;
            ssum += (p0 + p1) + (p2 + p3);
            __half2 hh;
            hh = __floats2half2_rn(p0, p1); pk[2 * u]     = *(uint32_t*)&hh;
            hh = __floats2half2_rn(p2, p3); pk[2 * u + 1] = *(uint32_t*)&hh;
        }
        {
            char* dst = psmC + prow * 144 + pc0 * 2;
            *(uint4*)dst        = make_uint4(pk[0], pk[1], pk[2], pk[3]);
            *(uint4*)(dst + 16) = make_uint4(pk[4], pk[5], pk[6], pk[7]);
        }
        __syncthreads();   // P published

        // ---- Phase 2: MMA via dual ldmatrix ----
        uint32_t lmB = sbase + (uint32_t)(buf * WHTILE_WORDS * 4) + lmB_off;
        uint32_t lmA = psm_base + (uint32_t)(mr * 144) + lmA_off;
#pragma unroll
        for (int k = 0; k < 4; k++) {
            uint32_t av[2][4];
#pragma unroll
            for (int mt = 0; mt < 2; mt++) {
                asm volatile(
                    "ldmatrix.sync.aligned.m8n8.x4.shared.b16 {%0,%1,%2,%3}, [%4];"
                    : "=r"(av[mt][0]), "=r"(av[mt][1]), "=r"(av[mt][2]), "=r"(av[mt][3])
                    : "r"(lmA + (uint32_t)(mt * 16 * 144 + k * 32)));
            }
#pragma unroll
            for (int p = 0; p < 4; p++) {
                uint32_t b00, b01, b10, b11;
                asm volatile(
                    "ldmatrix.sync.aligned.m8n8.x4.shared.b16 {%0,%1,%2,%3}, [%4];"
                    : "=r"(b00), "=r"(b01), "=r"(b10), "=r"(b11)
                    : "r"(lmB + (uint32_t)(p * 16 * 144 + k * 32)));
                mma_f16(acc[2 * p][0],     av[0][0], av[0][1], av[0][2], av[0][3], b00, b01);
                mma_f16(acc[2 * p][1],     av[1][0], av[1][1], av[1][2], av[1][3], b00, b01);
                mma_f16(acc[2 * p + 1][0], av[0][0], av[0][1], av[0][2], av[0][3], b10, b11);
                mma_f16(acc[2 * p + 1][1], av[1][0], av[1][1], av[1][2], av[1][3], b10, b11);
            }
        }
    }

    // final flush
    {
        float sv = ssum + __shfl_xor_sync(0xffffffffu, ssum, 1);
        sv += __shfl_xor_sync(0xffffffffu, sv, 2);
        int base = cur_ib * M_TILE;
        if ((t & 3) == 0) atomicAdd(&d_ssum[base + prow], sv);
        float* np = &d_num[(size_t)base * FOUT];
#pragma unroll
        for (int n = 0; n < 8; n++) {
            int cc = nq * 64 + n * 8 + tID * 2;
#pragma unroll
            for (int mt = 0; mt < 2; mt++) {
                int ra = mr + mt * 16 + gID;
                atomicAdd(&np[(size_t)ra * FOUT + cc],           acc[n][mt][0]);
                atomicAdd(&np[(size_t)ra * FOUT + cc + 1],       acc[n][mt][1]);
                atomicAdd(&np[(size_t)(ra + 8) * FOUT + cc],     acc[n][mt][2]);
                atomicAdd(&np[(size_t)(ra + 8) * FOUT + cc + 1], acc[n][mt][3]);
            }
        }
    }
}

// ---------------- normalize + ELU (vectorized) ----------------
__global__ void elu_kernel(float* __restrict__ out) {
    int idx = blockIdx.x * 256 + threadIdx.x;     // one float4 per thread
    int row = idx >> 6;                           // 64 float4 per row
    float s = d_ssum[row];
    float4 v = *(const float4*)&d_num[(size_t)idx * 4];
    float4 o;
    float x;
    x = v.x / s; o.x = x > 0.f ? x : expm1f(x);
    x = v.y / s; o.y = x > 0.f ? x : expm1f(x);
    x = v.z / s; o.z = x > 0.f ? x : expm1f(x);
    x = v.w / s; o.w = x > 0.f ? x : expm1f(x);
    *(float4*)&out[(size_t)idx * 4] = o;
}

extern "C" void kernel_launch(void* const* d_in, const int* in_sizes, int n_in,
                              void* d_out, int out_size) {
    const float* h   = (const float*)d_in[0];
    const int*   adj = (const int*)d_in[1];
    const float* W   = (const float*)d_in[2];
    const float* a   = (const float*)d_in[3];
    float* out = (float*)d_out;

    cudaFuncSetAttribute(attn_mma, cudaFuncAttributeMaxDynamicSharedMemorySize, SMEM_DYN);
    cudaFuncSetAttribute(gemm_wh_mma, cudaFuncAttributeMaxDynamicSharedMemorySize, GSMEM_DYN);

    init_kernel<<<(Nn * FOUT) / 1024, 256>>>(W);
    gemm_wh_mma<<<Nn / GM, 256, GSMEM_DYN>>>(h, a);
    pexp_kernel<<<Nn / 256, 256>>>();
    attn_mma<<<NCTA, 512, SMEM_DYN>>>(adj);
    elu_kernel<<<(Nn * FOUT) / 1024, 256>>>(out);
}

// round 17
// speedup vs baseline: 1.0358x; 1.0343x over previous
#include <cuda_runtime.h>
#include <cuda_fp16.h>
#include <cstdint>

#define Nn     8192
#define FIN    512
#define FOUT   256
#define LALPHA 0.2f
#define M_TILE 128
#define KC     64
#define NBLK   (Nn / M_TILE)          // 64 row blocks
#define CPB    (Nn / KC)              // 128 chunks per row block
#define TOTSLOT (NBLK * CPB)          // 8192
#define NCTA   148

// attn smem layout (words)
#define WT_STRIDE_H 72                // half-tile k-stride (halfs) = 144 B rows
#define WHTILE_WORDS (FOUT * (WT_STRIDE_H / 2))   // 256*36 = 9216
#define ADJ_STRIDE 68
#define ADJTILE_WORDS (M_TILE * ADJ_STRIDE)       // 8704
#define SM_ADJ (2 * WHTILE_WORDS)                 // 18432
#define SM_FBD (SM_ADJ + 2 * ADJTILE_WORDS)       // 35840
#define SMEM_DYN ((SM_FBD + 2 * 192) * 4)         // 144896 B

// gemm_wh_mma tiles
#define GW_STRIDE 264
#define GWTILE_WORDS (KC * GW_STRIDE)             // 16896
#define GM      64
#define HS      68
#define HS_WORDS (GM * HS)                        // 4352
#define GSM_A   (2 * HS_WORDS + 2 * GWTILE_WORDS)
#define GSMEM_DYN ((GSM_A + 512) * 4)             // 172032 B

// ---------------- scratch (device globals: allowed) ----------------
__device__ __half d_WhhT[(size_t)FOUT * Nn];         // 4 MB half, [n][j]
__device__ float d_Wr[(size_t)FIN * FOUT];           // tf32-rounded W
__device__ float d_f1[Nn];
__device__ float d_f2[Nn];
__device__ float d_A[Nn];
__device__ float d_C[Nn];
__device__ float d_B[Nn];
__device__ float d_D[Nn];
__device__ int   d_gmaxkey;
__device__ float d_num[(size_t)Nn * FOUT];           // 8 MB (atomic accum)
__device__ float d_ssum[Nn];

__device__ __forceinline__ uint32_t tf32_bits(float x) {
    uint32_t r; asm("cvt.rna.tf32.f32 %0, %1;" : "=r"(r) : "f"(x)); return r;
}
__device__ __forceinline__ void mma_tf32(float* d, uint32_t a0, uint32_t a1,
                                         uint32_t a2, uint32_t a3,
                                         uint32_t b0, uint32_t b1) {
    asm volatile(
        "mma.sync.aligned.m16n8k8.row.col.f32.tf32.tf32.f32 "
        "{%0,%1,%2,%3}, {%4,%5,%6,%7}, {%8,%9}, {%0,%1,%2,%3};"
        : "+f"(d[0]), "+f"(d[1]), "+f"(d[2]), "+f"(d[3])
        : "r"(a0), "r"(a1), "r"(a2), "r"(a3), "r"(b0), "r"(b1));
}
__device__ __forceinline__ void mma_f16(float* d, uint32_t a0, uint32_t a1,
                                        uint32_t a2, uint32_t a3,
                                        uint32_t b0, uint32_t b1) {
    asm volatile(
        "mma.sync.aligned.m16n8k16.row.col.f32.f16.f16.f32 "
        "{%0,%1,%2,%3}, {%4,%5,%6,%7}, {%8,%9}, {%0,%1,%2,%3};"
        : "+f"(d[0]), "+f"(d[1]), "+f"(d[2]), "+f"(d[3])
        : "r"(a0), "r"(a1), "r"(a2), "r"(a3), "r"(b0), "r"(b1));
}
__device__ __forceinline__ uint32_t smem_u32(const void* p) {
    uint32_t a;
    asm("{ .reg .u64 t; cvta.to.shared.u64 t, %1; cvt.u32.u64 %0, t; }"
        : "=r"(a) : "l"(p));
    return a;
}
__device__ __forceinline__ void cp_async16(uint32_t sa, const void* g) {
    asm volatile("cp.async.ca.shared.global [%0], [%1], 16;" :: "r"(sa), "l"(g) : "memory");
}
__device__ __forceinline__ void cp_commit() {
    asm volatile("cp.async.commit_group;" ::: "memory");
}
template <int N> __device__ __forceinline__ void cp_wait() {
    asm volatile("cp.async.wait_group %0;" :: "n"(N) : "memory");
}

// ---------------- init: zero accumulators + round W ----------------
__global__ void init_kernel(const float* __restrict__ W) {
    if (blockIdx.x == 0 && threadIdx.x == 0) d_gmaxkey = (int)0x80000000;
    size_t i = ((size_t)blockIdx.x * 256 + threadIdx.x) * 4;
    *(float4*)&d_num[i] = make_float4(0.f, 0.f, 0.f, 0.f);
    if (i < Nn)
        *(float4*)&d_ssum[i] = make_float4(0.f, 0.f, 0.f, 0.f);
    if (i < (size_t)FIN * FOUT) {
        float4 v = *(const float4*)&W[i];
        float4 o;
        o.x = __uint_as_float(tf32_bits(v.x));
        o.y = __uint_as_float(tf32_bits(v.y));
        o.z = __uint_as_float(tf32_bits(v.z));
        o.w = __uint_as_float(tf32_bits(v.w));
        *(float4*)&d_Wr[i] = o;
    }
}

// ---------------- Wh = h @ W via mma.sync tf32 (+ fused f1/f2/max) ----------------
__device__ __forceinline__ void stage_g(uint32_t sbase, const float* __restrict__ h,
                                        int i0, int c, int t) {
    int buf = c & 1;
    int k0  = c * KC;
    uint32_t hb = sbase + (uint32_t)(buf * HS_WORDS * 4);
#pragma unroll
    for (int u = 0; u < 4; u++) {
        int f = u * 256 + t;
        int row = f >> 4, seg = (f & 15) << 2;
        cp_async16(hb + (uint32_t)((row * HS + seg) * 4),
                   &h[(size_t)(i0 + row) * FIN + k0 + seg]);
    }
    uint32_t wb = sbase + (uint32_t)((2 * HS_WORDS + buf * GWTILE_WORDS) * 4);
#pragma unroll
    for (int u = 0; u < 16; u++) {
        int f = u * 256 + t;
        int row = f >> 6, c4 = (f & 63) << 2;
        cp_async16(wb + (uint32_t)((row * GW_STRIDE + c4) * 4),
                   &d_Wr[(size_t)(k0 + row) * FOUT + c4]);
    }
}

__global__ void __launch_bounds__(256, 1) gemm_wh_mma(const float* __restrict__ h,
                                                      const float* __restrict__ a) {
    extern __shared__ float gsm[];
    uint32_t sbase = smem_u32(gsm);
    float* as = gsm + GSM_A;   // a1[256] then a2[256]

    int t    = threadIdx.x;
    int lane = t & 31, wid = t >> 5;
    int mstrip = wid >> 1, nhalf = wid & 1;
    int gID = lane >> 2, tID = lane & 3;
    int r0t = mstrip * 16 + gID;
    int i0  = blockIdx.x * GM;

    if (t < 128) *(float4*)&as[t * 4] = *(const float4*)&a[t * 4];

    float acc[16][4];
#pragma unroll
    for (int n = 0; n < 16; n++)
#pragma unroll
        for (int u = 0; u < 4; u++) acc[n][u] = 0.f;

    stage_g(sbase, h, i0, 0, t);
    cp_commit();

    for (int c = 0; c < FIN / KC; c++) {
        int buf = c & 1;
        cp_wait<0>();
        __syncthreads();
        if (c + 1 < FIN / KC) {
            stage_g(sbase, h, i0, c + 1, t);
            cp_commit();
        }
        const float* hs = gsm + buf * HS_WORDS;
        const float* Wb = gsm + 2 * HS_WORDS + buf * GWTILE_WORDS;
#pragma unroll
        for (int k = 0; k < 8; k++) {
            int kc = tID + 8 * k;
            uint32_t a0 = tf32_bits(hs[(r0t)     * HS + kc]);
            uint32_t a1 = tf32_bits(hs[(r0t + 8) * HS + kc]);
            uint32_t a2 = tf32_bits(hs[(r0t)     * HS + kc + 4]);
            uint32_t a3 = tf32_bits(hs[(r0t + 8) * HS + kc + 4]);
            int krow = k * 8 + tID;
#pragma unroll
            for (int n = 0; n < 16; n++) {
                int n0 = nhalf * 128 + n * 8 + gID;
                uint32_t b0 = __float_as_uint(Wb[krow * GW_STRIDE + n0]);
                uint32_t b1 = __float_as_uint(Wb[(krow + 4) * GW_STRIDE + n0]);
                mma_tf32(acc[n], a0, a1, a2, a3, b0, b1);
            }
        }
        __syncthreads();
    }

    // epilogue: half WhhT (transposed [n][j]) + fused f1/f2 + block max(f2)
    float s1a = 0.f, s2a = 0.f, s1b = 0.f, s2b = 0.f;
    int cb = nhalf * 128 + tID * 2;
    int ia  = i0 + r0t, ib2 = i0 + r0t + 8;
#pragma unroll
    for (int n = 0; n < 16; n++) {
        int cc = cb + n * 8;
        d_WhhT[(size_t)cc * Nn + ia]        = __float2half(acc[n][0]);
        d_WhhT[(size_t)(cc + 1) * Nn + ia]  = __float2half(acc[n][1]);
        d_WhhT[(size_t)cc * Nn + ib2]       = __float2half(acc[n][2]);
        d_WhhT[(size_t)(cc + 1) * Nn + ib2] = __float2half(acc[n][3]);
        float a10 = as[cc], a11 = as[cc + 1];
        float a20 = as[256 + cc], a21 = as[256 + cc + 1];
        s1a += acc[n][0] * a10 + acc[n][1] * a11;
        s2a += acc[n][0] * a20 + acc[n][1] * a21;
        s1b += acc[n][2] * a10 + acc[n][3] * a11;
        s2b += acc[n][2] * a20 + acc[n][3] * a21;
    }
#pragma unroll
    for (int o = 1; o <= 2; o <<= 1) {
        s1a += __shfl_xor_sync(0xffffffffu, s1a, o);
        s2a += __shfl_xor_sync(0xffffffffu, s2a, o);
        s1b += __shfl_xor_sync(0xffffffffu, s1b, o);
        s2b += __shfl_xor_sync(0xffffffffu, s2b, o);
    }
    if (nhalf == 1 && tID == 0) {
        gsm[r0t]       = s1a;  gsm[64 + r0t]      = s2a;
        gsm[r0t + 8]   = s1b;  gsm[64 + r0t + 8]  = s2b;
    }
    __syncthreads();
    float mx = -3.0e38f;
    if (nhalf == 0 && tID == 0) {
        float f1t = s1a + gsm[r0t],     f2t = s2a + gsm[64 + r0t];
        float f1u = s1b + gsm[r0t + 8], f2u = s2b + gsm[64 + r0t + 8];
        d_f1[i0 + r0t]     = f1t;  d_f2[i0 + r0t]     = f2t;
        d_f1[i0 + r0t + 8] = f1u;  d_f2[i0 + r0t + 8] = f2u;
        mx = fmaxf(f2t, f2u);
    }
#pragma unroll
    for (int o = 16; o; o >>= 1)
        mx = fmaxf(mx, __shfl_xor_sync(0xffffffffu, mx, o));
    if (lane == 0) gsm[128 + wid] = mx;
    __syncthreads();
    if (t == 0) {
        float m = gsm[128];
#pragma unroll
        for (int w = 1; w < 8; w++) m = fmaxf(m, gsm[128 + w]);
        int b = __float_as_int(m);
        int key = b >= 0 ? b : (b ^ 0x7fffffff);
        atomicMax(&d_gmaxkey, key);
    }
}

// ---------------- factorized softmax weights ----------------
__global__ void pexp_kernel() {
    int i = blockIdx.x * 256 + threadIdx.x;
    int kk = d_gmaxkey;
    float gm = __int_as_float(kk >= 0 ? kk : (kk ^ 0x7fffffff));
    float f1 = d_f1[i], f2 = d_f2[i];
    float u  = f1 + gm;
    float m  = u > 0.f ? u : LALPHA * u;
    d_A[i] = __expf(u - m);
    d_C[i] = __expf(LALPHA * u - m);
    float v = f2 - gm;
    d_B[i] = __expf(v);
    d_D[i] = __expf(LALPHA * v);
}

// ---------------- staging helpers (cp.async) ----------------
__device__ __forceinline__ void stage_slot(uint32_t sbase, const int* adj,
                                           int s, int t) {
    int buf = s & 1;
    int ib  = s >> 7;
    int jg  = (s & (CPB - 1)) * KC;
    // WhT half tile [256 n][64 j], stride 72 halfs (144 B)
    uint32_t wb = sbase + (uint32_t)(buf * WHTILE_WORDS * 4);
#pragma unroll
    for (int u = 0; u < 4; u++) {
        int f = u * 512 + t;                  // 0..2047
        int row = f >> 3, seg = f & 7;        // 8 x 16B per row
        cp_async16(wb + (uint32_t)(row * 144 + seg * 16),
                   &d_WhhT[(size_t)row * Nn + jg + seg * 8]);
    }
    uint32_t ab = sbase + (uint32_t)((SM_ADJ + buf * ADJTILE_WORDS) * 4);
    const int* abase = adj + (size_t)ib * M_TILE * Nn + jg;
#pragma unroll
    for (int u = 0; u < 4; u++) {
        int f = u * 512 + t;
        int row = f >> 4, seg = (f & 15) << 2;
        cp_async16(ab + (uint32_t)((row * ADJ_STRIDE + seg) * 4),
                   abase + (size_t)row * Nn + seg);
    }
    if (t < 48) {
        uint32_t fb = sbase + (uint32_t)((SM_FBD + buf * 192 + t * 4) * 4);
        const float* src = (t < 16) ? &d_f2[jg + t * 4]
                         : (t < 32) ? &d_B[jg + (t - 16) * 4]
                                    : &d_D[jg + (t - 32) * 4];
        cp_async16(fb, src);
    }
}

// ---------------- fused attention: inline-P + ldmatrix fp16 MMA, 4x4 tiling ----------
// 148 CTAs x 512 threads = 16 warps: 4 m-strips (32 rows) x 4 n-quarters (64 cols).
// One sync per chunk. P computed inline in registers (dup 4x across n-quarters);
// B-frags via ldmatrix.x4 (dup 4x across m-strips). 64 HMMA/warp/chunk.
__global__ void __launch_bounds__(512, 1) attn_mma(const int* __restrict__ adj) {
    extern __shared__ float sm[];
    uint32_t sbase = smem_u32(sm);

    int t    = threadIdx.x;
    int lane = t & 31, wid = t >> 5;
    int mstrip = wid >> 2, nq = wid & 3;
    int gID = lane >> 2, tID = lane & 3;
    int mr  = mstrip * 32;

    // ldmatrix B lane offset
    int lq = lane >> 3, lr = lane & 7;
    int nB = ((lq >> 1) << 3) + lr, kB = (lq & 1) << 3;
    uint32_t lmB_off = (uint32_t)(((nq * 64 + nB) * WT_STRIDE_H + kB) * 2);

    int s0 = (int)(((long long)blockIdx.x * TOTSLOT) / NCTA);
    int s1 = (int)(((long long)(blockIdx.x + 1) * TOTSLOT) / NCTA);

    float acc[8][2][4];
#pragma unroll
    for (int n = 0; n < 8; n++)
#pragma unroll
        for (int mt = 0; mt < 2; mt++)
#pragma unroll
            for (int u = 0; u < 4; u++) acc[n][mt][u] = 0.f;
    float ssum[4] = {0.f, 0.f, 0.f, 0.f};

    float f1c[4], Ac[4], Cc[4];
    int cur_ib = -1;

    stage_slot(sbase, adj, s0, t);
    cp_commit();

    for (int s = s0; s < s1; s++) {
        int ib = s >> 7;
        int buf = s & 1;

        if (ib != cur_ib) {
            if (cur_ib >= 0) {
                int base = cur_ib * M_TILE;
#pragma unroll
                for (int q = 0; q < 4; q++) {
                    float sv = ssum[q];
                    sv += __shfl_xor_sync(0xffffffffu, sv, 1);
                    sv += __shfl_xor_sync(0xffffffffu, sv, 2);
                    if (tID == 0 && nq == 0)
                        atomicAdd(&d_ssum[base + mr + q * 8 + gID], sv);
                    ssum[q] = 0.f;
                }
                float* np = &d_num[(size_t)base * FOUT];
#pragma unroll
                for (int n = 0; n < 8; n++) {
                    int cc = nq * 64 + n * 8 + tID * 2;
#pragma unroll
                    for (int mt = 0; mt < 2; mt++) {
                        int ra = mr + mt * 16 + gID;
                        atomicAdd(&np[(size_t)ra * FOUT + cc],           acc[n][mt][0]);
                        atomicAdd(&np[(size_t)ra * FOUT + cc + 1],       acc[n][mt][1]);
                        atomicAdd(&np[(size_t)(ra + 8) * FOUT + cc],     acc[n][mt][2]);
                        atomicAdd(&np[(size_t)(ra + 8) * FOUT + cc + 1], acc[n][mt][3]);
                        acc[n][mt][0] = 0.f; acc[n][mt][1] = 0.f;
                        acc[n][mt][2] = 0.f; acc[n][mt][3] = 0.f;
                    }
                }
            }
            int base = ib * M_TILE;
#pragma unroll
            for (int q = 0; q < 4; q++) {
                int r = base + mr + q * 8 + gID;
                f1c[q] = d_f1[r];
                Ac[q]  = d_A[r];
                Cc[q]  = d_C[r];
            }
            cur_ib = ib;
        }

        cp_wait<0>();
        __syncthreads();   // staged bufs(s) ready; MMA(s-1) retired

        if (s + 1 < s1) {
            stage_slot(sbase, adj, s + 1, t);
            cp_commit();
        }

        const int*   adjS = (const int*)(sm + SM_ADJ + buf * ADJTILE_WORDS);
        const float* fbd  = sm + SM_FBD + buf * 192;
        uint32_t lmB = sbase + (uint32_t)(buf * WHTILE_WORDS * 4) + lmB_off;

#pragma unroll
        for (int k = 0; k < 4; k++) {
            int j0 = 2 * tID + 16 * k;
            int j8 = j0 + 8;
            float2 f2v0 = *(const float2*)&fbd[j0];
            float2 f2v8 = *(const float2*)&fbd[j8];
            float2 Bv0  = *(const float2*)&fbd[64 + j0];
            float2 Bv8  = *(const float2*)&fbd[64 + j8];
            float2 Dv0  = *(const float2*)&fbd[128 + j0];
            float2 Dv8  = *(const float2*)&fbd[128 + j8];

            uint32_t afr[2][4];    // [m-tile][a0..a3]
#pragma unroll
            for (int mt = 0; mt < 2; mt++) {
#pragma unroll
                for (int qh = 0; qh < 2; qh++) {        // row mr+mt*16+qh*8+gID
                    int q = mt * 2 + qh;
                    int rr = mr + q * 8 + gID;
                    int2 ad0 = *(const int2*)&adjS[rr * ADJ_STRIDE + j0];
                    int2 ad8 = *(const int2*)&adjS[rr * ADJ_STRIDE + j8];
                    float f1r = f1c[q], Ar = Ac[q], Cr = Cc[q];
                    float e0 = f1r + f2v0.x, e1 = f1r + f2v0.y;
                    float e8 = f1r + f2v8.x, e9 = f1r + f2v8.y;
                    float p0 = (ad0.x > 0) ? (e0 > 0.f ? Ar * Bv0.x : Cr * Dv0.x) : 0.f;
                    float p1 = (ad0.y > 0) ? (e1 > 0.f ? Ar * Bv0.y : Cr * Dv0.y) : 0.f;
                    float p8 = (ad8.x > 0) ? (e8 > 0.f ? Ar * Bv8.x : Cr * Dv8.x) : 0.f;
                    float p9 = (ad8.y > 0) ? (e9 > 0.f ? Ar * Bv8.y : Cr * Dv8.y) : 0.f;
                    if (nq == 0) ssum[q] += (p0 + p1) + (p8 + p9);
                    __half2 hh;
                    hh = __floats2half2_rn(p0, p1);
                    afr[mt][qh]     = *(uint32_t*)&hh;     // a0 (qh=0) / a1 (qh=1)
                    hh = __floats2half2_rn(p8, p9);
                    afr[mt][2 + qh] = *(uint32_t*)&hh;     // a2 (qh=0) / a3 (qh=1)
                }
            }

#pragma unroll
            for (int p = 0; p < 4; p++) {
                uint32_t b00, b01, b10, b11;
                asm volatile(
                    "ldmatrix.sync.aligned.m8n8.x4.shared.b16 {%0,%1,%2,%3}, [%4];"
                    : "=r"(b00), "=r"(b01), "=r"(b10), "=r"(b11)
                    : "r"(lmB + (uint32_t)(p * 16 * 144 + k * 32)));
                mma_f16(acc[2 * p][0],     afr[0][0], afr[0][1], afr[0][2], afr[0][3], b00, b01);
                mma_f16(acc[2 * p][1],     afr[1][0], afr[1][1], afr[1][2], afr[1][3], b00, b01);
                mma_f16(acc[2 * p + 1][0], afr[0][0], afr[0][1], afr[0][2], afr[0][3], b10, b11);
                mma_f16(acc[2 * p + 1][1], afr[1][0], afr[1][1], afr[1][2], afr[1][3], b10, b11);
            }
        }
    }

    // final flush
    {
        int base = cur_ib * M_TILE;
#pragma unroll
        for (int q = 0; q < 4; q++) {
            float sv = ssum[q];
            sv += __shfl_xor_sync(0xffffffffu, sv, 1);
            sv += __shfl_xor_sync(0xffffffffu, sv, 2);
            if (tID == 0 && nq == 0)
                atomicAdd(&d_ssum[base + mr + q * 8 + gID], sv);
        }
        float* np = &d_num[(size_t)base * FOUT];
#pragma unroll
        for (int n = 0; n < 8; n++) {
            int cc = nq * 64 + n * 8 + tID * 2;
#pragma unroll
            for (int mt = 0; mt < 2; mt++) {
                int ra = mr + mt * 16 + gID;
                atomicAdd(&np[(size_t)ra * FOUT + cc],           acc[n][mt][0]);
                atomicAdd(&np[(size_t)ra * FOUT + cc + 1],       acc[n][mt][1]);
                atomicAdd(&np[(size_t)(ra + 8) * FOUT + cc],     acc[n][mt][2]);
                atomicAdd(&np[(size_t)(ra + 8) * FOUT + cc + 1], acc[n][mt][3]);
            }
        }
    }
}

// ---------------- normalize + ELU (vectorized) ----------------
__global__ void elu_kernel(float* __restrict__ out) {
    int idx = blockIdx.x * 256 + threadIdx.x;     // one float4 per thread
    int row = idx >> 6;                           // 64 float4 per row
    float s = d_ssum[row];
    float4 v = *(const float4*)&d_num[(size_t)idx * 4];
    float4 o;
    float x;
    x = v.x / s; o.x = x > 0.f ? x : expm1f(x);
    x = v.y / s; o.y = x > 0.f ? x : expm1f(x);
    x = v.z / s; o.z = x > 0.f ? x : expm1f(x);
    x = v.w / s; o.w = x > 0.f ? x : expm1f(x);
    *(float4*)&out[(size_t)idx * 4] = o;
}

extern "C" void kernel_launch(void* const* d_in, const int* in_sizes, int n_in,
                              void* d_out, int out_size) {
    const float* h   = (const float*)d_in[0];
    const int*   adj = (const int*)d_in[1];
    const float* W   = (const float*)d_in[2];
    const float* a   = (const float*)d_in[3];
    float* out = (float*)d_out;

    cudaFuncSetAttribute(attn_mma, cudaFuncAttributeMaxDynamicSharedMemorySize, SMEM_DYN);
    cudaFuncSetAttribute(gemm_wh_mma, cudaFuncAttributeMaxDynamicSharedMemorySize, GSMEM_DYN);

    init_kernel<<<(Nn * FOUT) / 1024, 256>>>(W);
    gemm_wh_mma<<<Nn / GM, 256, GSMEM_DYN>>>(h, a);
    pexp_kernel<<<Nn / 256, 256>>>();
    attn_mma<<<NCTA, 512, SMEM_DYN>>>(adj);
    elu_kernel<<<(Nn * FOUT) / 1024, 256>>>(out);
}